// round 11
// baseline (speedup 1.0000x reference)
#include <cuda_runtime.h>
#include <cuda_bf16.h>
#include <mma.h>
#include <cstdint>

using namespace nvcuda;

#define D 64
#define KC 400
#define MTILE 128
#define NCH 80          // 5 chunks x 80 = 400, zero padding
#define NCHUNKS 5
#define TPB 256
#define XLD 72          // bf16 leading dim for x tiles (mult of 8)
#define ELD 72          // bf16 leading dim for e tiles
#define SLD 84          // f32 leading dim for score tile (mult of 4)

// smem byte offsets
#define OFF_XH 0                    // bf16[128][72] x3
#define OFF_XM 18432
#define OFF_XL 36864
#define OFF_UN 55296                // union: e-splits (3x 80*72*2=11520) | scores f32[128][84]
#define OFF_EH OFF_UN
#define OFF_EM (OFF_UN + 11520)
#define OFF_EL (OFF_UN + 23040)
#define OFF_SC OFF_UN               // scores overlay e (sync-separated phases)
#define OFF_N2 98304                // f32[80]
#define OFF_RW 98624                // int[128]
#define SMEM_BYTES 99136

// 3-way bf16 split: a ~= h + m + l (each captures ~8 mantissa bits)
static __device__ __forceinline__ void split3(float a, __nv_bfloat16 &h,
                                              __nv_bfloat16 &m, __nv_bfloat16 &l) {
    h = __float2bfloat16(a);
    float r = a - __bfloat162float(h);
    m = __float2bfloat16(r);
    float r2 = r - __bfloat162float(m);
    l = __float2bfloat16(r2);
}

__global__ void __launch_bounds__(TPB, 2)
vq_wmma_kernel(const float* __restrict__ x, const float* __restrict__ emb,
               float* __restrict__ out, int nrows) {
    extern __shared__ char sm[];
    float* n2 = (float*)(sm + OFF_N2);
    int*   rw = (int*)(sm + OFF_RW);
    float* sc = (float*)(sm + OFF_SC);

    const int tid = threadIdx.x;
    const int wid = tid >> 5;
    const int row0 = blockIdx.x * MTILE;

    // ---- stage x tile: 3 bf16 split tiles, [row][d] row-major ----
    for (int i = tid; i < MTILE * D; i += TPB) {
        int row = i >> 6, d = i & 63;
        float v = x[(size_t)(row0 + row) * D + d];
        __nv_bfloat16 h, m, l;
        split3(v, h, m, l);
        ((__nv_bfloat16*)(sm + OFF_XH))[row * XLD + d] = h;
        ((__nv_bfloat16*)(sm + OFF_XM))[row * XLD + d] = m;
        ((__nv_bfloat16*)(sm + OFF_XL))[row * XLD + d] = l;
    }

    float best = -3.4e38f;
    int bidx = 0;

    // split-pair schedule: hh, hm, mh, mm, hl, lh (dropped terms ~1e-8 << fp32 noise)
    const int AOF[6] = {OFF_XH, OFF_XH, OFF_XM, OFF_XM, OFF_XH, OFF_XL};
    const int BOF[6] = {OFF_EH, OFF_EM, OFF_EH, OFF_EM, OFF_EL, OFF_EH};

    for (int c = 0; c < NCHUNKS; c++) {
        const int g0 = c * NCH;
        __syncthreads();   // prior scan done before union region is overwritten (also fences x stage on c=0)

        // ---- stage e chunk: 3 bf16 split tiles, [code][d] ----
        for (int i = tid; i < NCH * D; i += TPB) {
            int code = i >> 6, d = i & 63;
            float v = emb[(size_t)(g0 + code) * D + d];
            __nv_bfloat16 h, m, l;
            split3(v, h, m, l);
            ((__nv_bfloat16*)(sm + OFF_EH))[code * ELD + d] = h;
            ((__nv_bfloat16*)(sm + OFF_EM))[code * ELD + d] = m;
            ((__nv_bfloat16*)(sm + OFF_EL))[code * ELD + d] = l;
        }
        // ---- -0.5*||e||^2 in fp32 ----
        if (tid < NCH) {
            const float* e = emb + (size_t)(g0 + tid) * D;
            float a = 0.f;
            #pragma unroll 16
            for (int d = 0; d < D; d++) a = fmaf(e[d], e[d], a);
            n2[tid] = -0.5f * a;
        }
        __syncthreads();

        // ---- wmma: warp wid owns rows 16*wid..16*wid+15, all 80 codes ----
        wmma::fragment<wmma::accumulator, 16, 16, 16, float> acc[5];
        #pragma unroll
        for (int nf = 0; nf < 5; nf++) wmma::fill_fragment(acc[nf], 0.0f);

        #pragma unroll
        for (int s = 0; s < 6; s++) {
            const __nv_bfloat16* ap = (const __nv_bfloat16*)(sm + AOF[s]) + wid * 16 * XLD;
            const __nv_bfloat16* bp = (const __nv_bfloat16*)(sm + BOF[s]);
            #pragma unroll
            for (int k = 0; k < 4; k++) {
                wmma::fragment<wmma::matrix_a, 16, 16, 16, __nv_bfloat16, wmma::row_major> af;
                wmma::load_matrix_sync(af, ap + k * 16, XLD);
                #pragma unroll
                for (int nf = 0; nf < 5; nf++) {
                    wmma::fragment<wmma::matrix_b, 16, 16, 16, __nv_bfloat16, wmma::col_major> bf;
                    // B(k,n) = e[n][k]: col_major with ldm=ELD
                    wmma::load_matrix_sync(bf, bp + nf * 16 * ELD + k * 16, ELD);
                    wmma::mma_sync(acc[nf], af, bf, acc[nf]);
                }
            }
        }

        __syncthreads();   // all warps done reading e splits before scores overwrite union
        #pragma unroll
        for (int nf = 0; nf < 5; nf++)
            wmma::store_matrix_sync(sc + wid * 16 * SLD + nf * 16, acc[nf], SLD,
                                    wmma::mem_row_major);
        __syncthreads();

        // ---- fused argmin scan: thread t (<128) owns row t ----
        if (tid < MTILE) {
            const float* srow = sc + tid * SLD;
            #pragma unroll 8
            for (int j = 0; j < NCH; j++) {
                float s = srow[j] + n2[j];
                // strict >, ascending j & chunks: first-max == jnp.argmin first-min
                if (s > best) { best = s; bidx = g0 + j; }
            }
        }
    }

    // ---- winners to smem, cooperative coalesced gather ----
    if (tid < MTILE) rw[tid] = bidx;
    __syncthreads();

    const float4* eg = (const float4*)emb;
    float4* og = (float4*)(out + (size_t)row0 * D);
    for (int i = tid; i < MTILE * 16; i += TPB) {
        int r = i >> 4, q = i & 15;
        og[r * 16 + q] = eg[(size_t)rw[r] * 16 + q];
    }
}

extern "C" void kernel_launch(void* const* d_in, const int* in_sizes, int n_in,
                              void* d_out, int out_size) {
    const float* x   = (const float*)d_in[0];
    const float* emb = (const float*)d_in[1];
    float* out = (float*)d_out;

    int nrows = in_sizes[0] / D;   // 262144, divisible by MTILE

    cudaFuncSetAttribute(vq_wmma_kernel,
                         cudaFuncAttributeMaxDynamicSharedMemorySize, SMEM_BYTES);

    int blocks = nrows / MTILE;    // 2048
    vq_wmma_kernel<<<blocks, TPB, SMEM_BYTES>>>(x, emb, out, nrows);
}

// round 12
// speedup vs baseline: 1.5251x; 1.5251x over previous
#include <cuda_runtime.h>
#include <cuda_bf16.h>
#include <mma.h>
#include <cstdint>

using namespace nvcuda;

#define D 64
#define KC 400
#define MTILE 128
#define NCH 80          // 5 chunks x 80 = 400, no padding
#define NCHUNKS 5
#define TPB 256
#define XLD 72          // bf16 ld for x tiles (mult of 8)
#define ETLD 88         // bf16 ld for TRANSPOSED e tiles [d][code] (mult of 8)
#define SLD 84          // f32 ld for score tile (mult of 4)

// smem byte offsets
#define OFF_XH 0                    // bf16[128][72] x3
#define OFF_XM 18432
#define OFF_XL 36864
#define OFF_UN 55296                // union: eT splits (3 x 64*88*2=11264) | scores f32[128][84]
#define OFF_EH OFF_UN
#define OFF_EM (OFF_UN + 11264)
#define OFF_EL (OFF_UN + 22528)
#define OFF_SC OFF_UN               // scores overlay eT (sync-separated phases)
#define OFF_N2 98304                // f32[80]
#define OFF_RW 98624                // int[128]
#define SMEM_BYTES 99136

// 3-way bf16 split: a ~= h + m + l (each captures ~8 mantissa bits)
static __device__ __forceinline__ void split3(float a, __nv_bfloat16 &h,
                                              __nv_bfloat16 &m, __nv_bfloat16 &l) {
    h = __float2bfloat16(a);
    float r = a - __bfloat162float(h);
    m = __float2bfloat16(r);
    float r2 = r - __bfloat162float(m);
    l = __float2bfloat16(r2);
}

__global__ void __launch_bounds__(TPB, 2)
vq_wmma_kernel(const float* __restrict__ x, const float* __restrict__ emb,
               float* __restrict__ out, int nrows) {
    extern __shared__ char sm[];
    float* n2 = (float*)(sm + OFF_N2);
    int*   rw = (int*)(sm + OFF_RW);
    float* sc = (float*)(sm + OFF_SC);

    const int tid = threadIdx.x;
    const int wid = tid >> 5;
    const int row0 = blockIdx.x * MTILE;

    // ---- stage x tile: 3 bf16 split tiles, [row][d] row-major ----
    for (int i = tid; i < MTILE * D; i += TPB) {
        int row = i >> 6, d = i & 63;
        float v = x[(size_t)(row0 + row) * D + d];
        __nv_bfloat16 h, m, l;
        split3(v, h, m, l);
        ((__nv_bfloat16*)(sm + OFF_XH))[row * XLD + d] = h;
        ((__nv_bfloat16*)(sm + OFF_XM))[row * XLD + d] = m;
        ((__nv_bfloat16*)(sm + OFF_XL))[row * XLD + d] = l;
    }
    __syncthreads();

    // ---- hoist A fragments: chunk-invariant, 12 frags in registers ----
    wmma::fragment<wmma::matrix_a, 16, 16, 16, __nv_bfloat16, wmma::row_major> ah[4], am[4], al[4];
    {
        const __nv_bfloat16* xh = (const __nv_bfloat16*)(sm + OFF_XH) + wid * 16 * XLD;
        const __nv_bfloat16* xm = (const __nv_bfloat16*)(sm + OFF_XM) + wid * 16 * XLD;
        const __nv_bfloat16* xl = (const __nv_bfloat16*)(sm + OFF_XL) + wid * 16 * XLD;
        #pragma unroll
        for (int k = 0; k < 4; k++) {
            wmma::load_matrix_sync(ah[k], xh + k * 16, XLD);
            wmma::load_matrix_sync(am[k], xm + k * 16, XLD);
            wmma::load_matrix_sync(al[k], xl + k * 16, XLD);
        }
    }

    float best = -3.4e38f;
    int bidx = 0;

    for (int c = 0; c < NCHUNKS; c++) {
        const int g0 = c * NCH;
        __syncthreads();   // prior scan done before union region is overwritten

        // ---- stage e chunk TRANSPOSED: eT[d][code], 3 split tiles ----
        for (int i = tid; i < NCH * D; i += TPB) {
            int code = i >> 6, d = i & 63;           // consecutive tid = consecutive d: coalesced LDG
            float v = emb[(size_t)(g0 + code) * D + d];
            __nv_bfloat16 h, m, l;
            split3(v, h, m, l);
            ((__nv_bfloat16*)(sm + OFF_EH))[d * ETLD + code] = h;
            ((__nv_bfloat16*)(sm + OFF_EM))[d * ETLD + code] = m;
            ((__nv_bfloat16*)(sm + OFF_EL))[d * ETLD + code] = l;
        }
        // ---- -0.5*||e||^2 in fp32 ----
        if (tid < NCH) {
            const float* e = emb + (size_t)(g0 + tid) * D;
            float a = 0.f;
            #pragma unroll 16
            for (int d = 0; d < D; d++) a = fmaf(e[d], e[d], a);
            n2[tid] = -0.5f * a;
        }
        __syncthreads();

        // ---- MMAs: per (nf,k) load 3 B frags (row_major, fast), fire 6 MMAs ----
        wmma::fragment<wmma::accumulator, 16, 16, 16, float> acc[5];
        #pragma unroll
        for (int nf = 0; nf < 5; nf++) wmma::fill_fragment(acc[nf], 0.0f);

        const __nv_bfloat16* eh = (const __nv_bfloat16*)(sm + OFF_EH);
        const __nv_bfloat16* em = (const __nv_bfloat16*)(sm + OFF_EM);
        const __nv_bfloat16* el = (const __nv_bfloat16*)(sm + OFF_EL);

        #pragma unroll
        for (int nf = 0; nf < 5; nf++) {
            #pragma unroll
            for (int k = 0; k < 4; k++) {
                wmma::fragment<wmma::matrix_b, 16, 16, 16, __nv_bfloat16, wmma::row_major> bh, bm, bl;
                // B(k,n) = eT[k][n]: row_major, ldm=ETLD
                wmma::load_matrix_sync(bh, eh + k * 16 * ETLD + nf * 16, ETLD);
                wmma::load_matrix_sync(bm, em + k * 16 * ETLD + nf * 16, ETLD);
                wmma::load_matrix_sync(bl, el + k * 16 * ETLD + nf * 16, ETLD);
                wmma::mma_sync(acc[nf], ah[k], bh, acc[nf]);   // hh
                wmma::mma_sync(acc[nf], ah[k], bm, acc[nf]);   // hm
                wmma::mma_sync(acc[nf], am[k], bh, acc[nf]);   // mh
                wmma::mma_sync(acc[nf], am[k], bm, acc[nf]);   // mm
                wmma::mma_sync(acc[nf], ah[k], bl, acc[nf]);   // hl
                wmma::mma_sync(acc[nf], al[k], bh, acc[nf]);   // lh
            }
        }

        __syncthreads();   // all warps done reading eT before scores overwrite union
        #pragma unroll
        for (int nf = 0; nf < 5; nf++)
            wmma::store_matrix_sync(sc + wid * 16 * SLD + nf * 16, acc[nf], SLD,
                                    wmma::mem_row_major);
        __syncthreads();

        // ---- fused argmin scan: thread t (<128) owns row t ----
        if (tid < MTILE) {
            const float* srow = sc + tid * SLD;
            #pragma unroll 8
            for (int j = 0; j < NCH; j++) {
                float s = srow[j] + n2[j];
                // strict >, ascending j & chunks: first-max == jnp.argmin first-min
                if (s > best) { best = s; bidx = g0 + j; }
            }
        }
    }

    // ---- winners to smem, cooperative coalesced gather ----
    if (tid < MTILE) rw[tid] = bidx;
    __syncthreads();

    const float4* eg = (const float4*)emb;
    float4* og = (float4*)(out + (size_t)row0 * D);
    for (int i = tid; i < MTILE * 16; i += TPB) {
        int r = i >> 4, q = i & 15;
        og[r * 16 + q] = eg[(size_t)rw[r] * 16 + q];
    }
}

extern "C" void kernel_launch(void* const* d_in, const int* in_sizes, int n_in,
                              void* d_out, int out_size) {
    const float* x   = (const float*)d_in[0];
    const float* emb = (const float*)d_in[1];
    float* out = (float*)d_out;

    int nrows = in_sizes[0] / D;   // 262144, divisible by MTILE

    cudaFuncSetAttribute(vq_wmma_kernel,
                         cudaFuncAttributeMaxDynamicSharedMemorySize, SMEM_BYTES);

    int blocks = nrows / MTILE;    // 2048
    vq_wmma_kernel<<<blocks, TPB, SMEM_BYTES>>>(x, emb, out, nrows);
}

// round 13
// speedup vs baseline: 1.5994x; 1.0487x over previous
#include <cuda_runtime.h>
#include <cuda_bf16.h>
#include <mma.h>
#include <cstdint>

using namespace nvcuda;

#define D 64
#define KC 400
#define MTILE 128
#define NCH 80          // 5 chunks x 80 = 400, no padding
#define NCHUNKS 5
#define TPB 256
#define XLD 72          // bf16 ld for x tiles (mult of 8)
#define ETLD 88         // bf16 ld for TRANSPOSED e tiles [d][code] (mult of 8)
#define SLD 84          // f32 ld for score tile (mult of 4)

// smem byte offsets
#define OFF_XH 0                    // bf16[128][72] x3
#define OFF_XM 18432
#define OFF_XL 36864
#define OFF_UN 55296                // union: eT splits (3 x 64*88*2=11264) | scores f32[128][84]
#define OFF_EH OFF_UN
#define OFF_EM (OFF_UN + 11264)
#define OFF_EL (OFF_UN + 22528)
#define OFF_SC OFF_UN               // scores overlay eT (sync-separated phases)
#define OFF_N2 98304                // f32[80]
#define OFF_RW 98624                // int[128]
#define SMEM_BYTES 99136

// 3-way bf16 split: a ~= h + m + l (each captures ~8 mantissa bits)
static __device__ __forceinline__ void split3(float a, __nv_bfloat16 &h,
                                              __nv_bfloat16 &m, __nv_bfloat16 &l) {
    h = __float2bfloat16(a);
    float r = a - __bfloat162float(h);
    m = __float2bfloat16(r);
    float r2 = r - __bfloat162float(m);
    l = __float2bfloat16(r2);
}

__global__ void __launch_bounds__(TPB, 2)
vq_wmma_kernel(const float* __restrict__ x, const float* __restrict__ emb,
               float* __restrict__ out, int nrows) {
    extern __shared__ char sm[];
    float* n2 = (float*)(sm + OFF_N2);
    int*   rw = (int*)(sm + OFF_RW);
    float* sc = (float*)(sm + OFF_SC);

    const int tid = threadIdx.x;
    const int wid = tid >> 5;
    const int row0 = blockIdx.x * MTILE;

    // ---- stage x tile: 3 bf16 split tiles, [row][d] row-major ----
    for (int i = tid; i < MTILE * D; i += TPB) {
        int row = i >> 6, d = i & 63;
        float v = x[(size_t)(row0 + row) * D + d];
        __nv_bfloat16 h, m, l;
        split3(v, h, m, l);
        ((__nv_bfloat16*)(sm + OFF_XH))[row * XLD + d] = h;
        ((__nv_bfloat16*)(sm + OFF_XM))[row * XLD + d] = m;
        ((__nv_bfloat16*)(sm + OFF_XL))[row * XLD + d] = l;
    }

    float best = -3.4e38f;
    int bidx = 0;

    for (int c = 0; c < NCHUNKS; c++) {
        const int g0 = c * NCH;
        __syncthreads();   // prior scan (or x stage on c=0) done before union overwrite

        // ---- stage e chunk TRANSPOSED: eT[d][code], 3 split tiles ----
        for (int i = tid; i < NCH * D; i += TPB) {
            int code = i >> 6, d = i & 63;     // consecutive tid = consecutive d: coalesced LDG
            float v = emb[(size_t)(g0 + code) * D + d];
            __nv_bfloat16 h, m, l;
            split3(v, h, m, l);
            ((__nv_bfloat16*)(sm + OFF_EH))[d * ETLD + code] = h;
            ((__nv_bfloat16*)(sm + OFF_EM))[d * ETLD + code] = m;
            ((__nv_bfloat16*)(sm + OFF_EL))[d * ETLD + code] = l;
        }
        // ---- -0.5*||e||^2 in fp32 ----
        if (tid < NCH) {
            const float* e = emb + (size_t)(g0 + tid) * D;
            float a = 0.f;
            #pragma unroll 16
            for (int d = 0; d < D; d++) a = fmaf(e[d], e[d], a);
            n2[tid] = -0.5f * a;
        }
        __syncthreads();

        // ---- MMAs: k OUTER (A frags live only inside k iter -> no spill) ----
        wmma::fragment<wmma::accumulator, 16, 16, 16, float> acc[5];
        #pragma unroll
        for (int nf = 0; nf < 5; nf++) wmma::fill_fragment(acc[nf], 0.0f);

        const __nv_bfloat16* xh = (const __nv_bfloat16*)(sm + OFF_XH) + wid * 16 * XLD;
        const __nv_bfloat16* xm = (const __nv_bfloat16*)(sm + OFF_XM) + wid * 16 * XLD;
        const __nv_bfloat16* xl = (const __nv_bfloat16*)(sm + OFF_XL) + wid * 16 * XLD;
        const __nv_bfloat16* eh = (const __nv_bfloat16*)(sm + OFF_EH);
        const __nv_bfloat16* em = (const __nv_bfloat16*)(sm + OFF_EM);
        const __nv_bfloat16* el = (const __nv_bfloat16*)(sm + OFF_EL);

        #pragma unroll
        for (int k = 0; k < 4; k++) {
            wmma::fragment<wmma::matrix_a, 16, 16, 16, __nv_bfloat16, wmma::row_major> ah, am, al;
            wmma::load_matrix_sync(ah, xh + k * 16, XLD);
            wmma::load_matrix_sync(am, xm + k * 16, XLD);
            wmma::load_matrix_sync(al, xl + k * 16, XLD);
            #pragma unroll
            for (int nf = 0; nf < 5; nf++) {
                wmma::fragment<wmma::matrix_b, 16, 16, 16, __nv_bfloat16, wmma::row_major> bh, bm, bl;
                // B(k,n) = eT[k][n]: row_major, ldm=ETLD (ldmatrix fast path)
                wmma::load_matrix_sync(bh, eh + k * 16 * ETLD + nf * 16, ETLD);
                wmma::load_matrix_sync(bm, em + k * 16 * ETLD + nf * 16, ETLD);
                wmma::load_matrix_sync(bl, el + k * 16 * ETLD + nf * 16, ETLD);
                wmma::mma_sync(acc[nf], ah, bh, acc[nf]);   // hh
                wmma::mma_sync(acc[nf], ah, bm, acc[nf]);   // hm
                wmma::mma_sync(acc[nf], am, bh, acc[nf]);   // mh
                wmma::mma_sync(acc[nf], am, bm, acc[nf]);   // mm
                wmma::mma_sync(acc[nf], ah, bl, acc[nf]);   // hl
                wmma::mma_sync(acc[nf], al, bh, acc[nf]);   // lh
            }
        }

        __syncthreads();   // all warps done reading eT before scores overwrite union
        #pragma unroll
        for (int nf = 0; nf < 5; nf++)
            wmma::store_matrix_sync(sc + wid * 16 * SLD + nf * 16, acc[nf], SLD,
                                    wmma::mem_row_major);
        __syncthreads();

        // ---- fused argmin scan: thread t (<128) owns row t ----
        if (tid < MTILE) {
            const float* srow = sc + tid * SLD;
            #pragma unroll 8
            for (int j = 0; j < NCH; j++) {
                float s = srow[j] + n2[j];
                // strict >, ascending j & chunks: first-max == jnp.argmin first-min
                if (s > best) { best = s; bidx = g0 + j; }
            }
        }
    }

    // ---- winners to smem, cooperative coalesced gather ----
    if (tid < MTILE) rw[tid] = bidx;
    __syncthreads();

    const float4* eg = (const float4*)emb;
    float4* og = (float4*)(out + (size_t)row0 * D);
    for (int i = tid; i < MTILE * 16; i += TPB) {
        int r = i >> 4, q = i & 15;
        og[r * 16 + q] = eg[(size_t)rw[r] * 16 + q];
    }
}

extern "C" void kernel_launch(void* const* d_in, const int* in_sizes, int n_in,
                              void* d_out, int out_size) {
    const float* x   = (const float*)d_in[0];
    const float* emb = (const float*)d_in[1];
    float* out = (float*)d_out;

    int nrows = in_sizes[0] / D;   // 262144, divisible by MTILE

    cudaFuncSetAttribute(vq_wmma_kernel,
                         cudaFuncAttributeMaxDynamicSharedMemorySize, SMEM_BYTES);

    int blocks = nrows / MTILE;    // 2048
    vq_wmma_kernel<<<blocks, TPB, SMEM_BYTES>>>(x, emb, out, nrows);
}

// round 14
// speedup vs baseline: 2.7816x; 1.7392x over previous
#include <cuda_runtime.h>
#include <cuda_bf16.h>
#include <mma.h>
#include <cstdint>

using namespace nvcuda;

#define D 64
#define KC 400
#define MTILE 128
#define NCH 80
#define NCHUNKS 5
#define TPB 256
#define XTLD 136        // bf16 ld for xT tiles [d][row] (mult of 8)
#define ELD2 72         // bf16 ld for e tiles [code][d] (mult of 8)
#define SLD 164         // f32 ld for scoresT [code][row] (mult of 4)

// smem byte offsets
#define OFF_XTH 0                   // bf16[64][136] x3 (xT splits, persist whole kernel)
#define OFF_XTM 17408
#define OFF_XTL 34816
#define OFF_UN  52224               // union: norm partials | e tiles | scoresT
#define OFF_EH  OFF_UN              // bf16[80][72] x3 = 11520 each
#define OFF_EM  (OFF_UN + 11520)
#define OFF_EL  (OFF_UN + 23040)
#define OFF_SC  OFF_UN              // f32[80][164] = 52480 (overlay, sync-separated)
#define OFF_N2A 104704              // f32[400]
#define OFF_RW  106304              // int[128]
#define SMEM_BYTES 106880

// 3-way bf16 split: a ~= h + m + l (each captures ~8 mantissa bits)
static __device__ __forceinline__ void split3(float a, __nv_bfloat16 &h,
                                              __nv_bfloat16 &m, __nv_bfloat16 &l) {
    h = __float2bfloat16(a);
    float r = a - __bfloat162float(h);
    m = __float2bfloat16(r);
    float r2 = r - __bfloat162float(m);
    l = __float2bfloat16(r2);
}
static __device__ __forceinline__ uint32_t packbf(__nv_bfloat16 a, __nv_bfloat16 b) {
    return (uint32_t)__bfloat16_as_ushort(a) | ((uint32_t)__bfloat16_as_ushort(b) << 16);
}

__global__ void __launch_bounds__(TPB, 2)
vq_wmma_kernel(const float* __restrict__ x, const float* __restrict__ emb,
               float* __restrict__ out, int nrows) {
    extern __shared__ char sm[];
    float* n2a = (float*)(sm + OFF_N2A);
    int*   rw  = (int*)(sm + OFF_RW);
    float* sc  = (float*)(sm + OFF_SC);

    const int tid = threadIdx.x;
    const int wid = tid >> 5;
    const int row0 = blockIdx.x * MTILE;

    // ---- all 400 norms once: coalesced partial sums (8 threads/code) ----
    {
        float* part = (float*)(sm + OFF_UN);     // f32[400*8] overlay
        for (int i = tid; i < KC * 8; i += TPB) {
            int code = i >> 3, p = i & 7;
            const float2* e2 = (const float2*)(emb + (size_t)code * D + p * 8);
            float s = 0.f;
            #pragma unroll
            for (int q = 0; q < 4; q++) {
                float2 v = e2[q];
                s = fmaf(v.x, v.x, fmaf(v.y, v.y, s));
            }
            part[i] = s;
        }
        __syncthreads();
        for (int i = tid; i < KC; i += TPB) {
            float s = 0.f;
            #pragma unroll
            for (int p = 0; p < 8; p++) s += part[i * 8 + p];
            n2a[i] = -0.5f * s;
        }
    }

    // ---- stage xT once: [d][row] x3 splits; row-inner -> coalesced STS ----
    {
        const float4* xg = (const float4*)(x + (size_t)row0 * D);
        __nv_bfloat16* xth = (__nv_bfloat16*)(sm + OFF_XTH);
        __nv_bfloat16* xtm = (__nv_bfloat16*)(sm + OFF_XTM);
        __nv_bfloat16* xtl = (__nv_bfloat16*)(sm + OFF_XTL);
        for (int i = tid; i < MTILE * 16; i += TPB) {
            int row = i & 127, db = i >> 7;
            float4 v = xg[row * 16 + db];        // strided gather (one-time cost)
            float vv[4] = {v.x, v.y, v.z, v.w};
            #pragma unroll
            for (int cc = 0; cc < 4; cc++) {
                __nv_bfloat16 h, m, l;
                split3(vv[cc], h, m, l);
                int o = (4 * db + cc) * XTLD + row;   // consecutive row: coalesced
                xth[o] = h; xtm[o] = m; xtl[o] = l;
            }
        }
    }

    float best = -3.4e38f;
    int bidx = 0;

    for (int c = 0; c < NCHUNKS; c++) {
        const int g0 = c * NCH;
        __syncthreads();   // prior scan / init phases done before union overwrite

        // ---- stage e chunk NATURAL [code][d]: fully coalesced, no transpose ----
        for (int i = tid; i < NCH * 32; i += TPB) {
            int code = i >> 5, c2 = i & 31;
            float2 v = ((const float2*)(emb + (size_t)(g0 + code) * D))[c2];
            __nv_bfloat16 h0, m0, l0, h1, m1, l1;
            split3(v.x, h0, m0, l0);
            split3(v.y, h1, m1, l1);
            uint32_t o = OFF_EH + (uint32_t)(code * ELD2 + c2 * 2) * 2;
            *(uint32_t*)(sm + o)           = packbf(h0, h1);
            *(uint32_t*)(sm + o + 11520)   = packbf(m0, m1);
            *(uint32_t*)(sm + o + 23040)   = packbf(l0, l1);
        }
        __syncthreads();

        // ---- MMAs: scoresT = E * X^T.  A = e [code][d] rm, B = xT [d][row] rm ----
        wmma::fragment<wmma::accumulator, 16, 16, 16, float> acc[5];
        #pragma unroll
        for (int nf = 0; nf < 5; nf++) wmma::fill_fragment(acc[nf], 0.0f);

        const __nv_bfloat16* eh  = (const __nv_bfloat16*)(sm + OFF_EH);
        const __nv_bfloat16* em  = (const __nv_bfloat16*)(sm + OFF_EM);
        const __nv_bfloat16* el  = (const __nv_bfloat16*)(sm + OFF_EL);
        const __nv_bfloat16* xth = (const __nv_bfloat16*)(sm + OFF_XTH) + wid * 16;
        const __nv_bfloat16* xtm = (const __nv_bfloat16*)(sm + OFF_XTM) + wid * 16;
        const __nv_bfloat16* xtl = (const __nv_bfloat16*)(sm + OFF_XTL) + wid * 16;

        #pragma unroll
        for (int k = 0; k < 4; k++) {
            wmma::fragment<wmma::matrix_b, 16, 16, 16, __nv_bfloat16, wmma::row_major> bh, bm, bl;
            wmma::load_matrix_sync(bh, xth + k * 16 * XTLD, XTLD);
            wmma::load_matrix_sync(bm, xtm + k * 16 * XTLD, XTLD);
            wmma::load_matrix_sync(bl, xtl + k * 16 * XTLD, XTLD);
            #pragma unroll
            for (int nf = 0; nf < 5; nf++) {
                wmma::fragment<wmma::matrix_a, 16, 16, 16, __nv_bfloat16, wmma::row_major> ah, am, al;
                wmma::load_matrix_sync(ah, eh + nf * 16 * ELD2 + k * 16, ELD2);
                wmma::load_matrix_sync(am, em + nf * 16 * ELD2 + k * 16, ELD2);
                wmma::load_matrix_sync(al, el + nf * 16 * ELD2 + k * 16, ELD2);
                wmma::mma_sync(acc[nf], ah, bh, acc[nf]);   // hh
                wmma::mma_sync(acc[nf], ah, bm, acc[nf]);   // hm
                wmma::mma_sync(acc[nf], am, bh, acc[nf]);   // mh
                wmma::mma_sync(acc[nf], am, bm, acc[nf]);   // mm
                wmma::mma_sync(acc[nf], ah, bl, acc[nf]);   // hl
                wmma::mma_sync(acc[nf], al, bh, acc[nf]);   // lh
            }
        }

        __syncthreads();   // e readers done before scoresT overwrite union
        #pragma unroll
        for (int nf = 0; nf < 5; nf++)
            wmma::store_matrix_sync(sc + nf * 16 * SLD + wid * 16, acc[nf], SLD,
                                    wmma::mem_row_major);
        __syncthreads();

        // ---- fused argmin: thread t owns row t; lanes consecutive -> conflict-free ----
        if (tid < MTILE) {
            #pragma unroll 8
            for (int j = 0; j < NCH; j++) {
                float s = sc[j * SLD + tid] + n2a[g0 + j];
                // strict >, ascending j & chunks: first-max == jnp.argmin first-min
                if (s > best) { best = s; bidx = g0 + j; }
            }
        }
    }

    // ---- winners to smem, cooperative coalesced gather ----
    if (tid < MTILE) rw[tid] = bidx;
    __syncthreads();

    const float4* eg = (const float4*)emb;
    float4* og = (float4*)(out + (size_t)row0 * D);
    for (int i = tid; i < MTILE * 16; i += TPB) {
        int r = i >> 4, q = i & 15;
        og[r * 16 + q] = eg[(size_t)rw[r] * 16 + q];
    }
}

extern "C" void kernel_launch(void* const* d_in, const int* in_sizes, int n_in,
                              void* d_out, int out_size) {
    const float* x   = (const float*)d_in[0];
    const float* emb = (const float*)d_in[1];
    float* out = (float*)d_out;

    int nrows = in_sizes[0] / D;   // 262144, divisible by MTILE

    cudaFuncSetAttribute(vq_wmma_kernel,
                         cudaFuncAttributeMaxDynamicSharedMemorySize, SMEM_BYTES);

    int blocks = nrows / MTILE;    // 2048
    vq_wmma_kernel<<<blocks, TPB, SMEM_BYTES>>>(x, emb, out, nrows);
}

// round 15
// speedup vs baseline: 3.1234x; 1.1229x over previous
#include <cuda_runtime.h>
#include <cuda_bf16.h>
#include <mma.h>
#include <cstdint>

using namespace nvcuda;

#define D 64
#define KC 400
#define MTILE 128
#define NCH 80
#define NCHUNKS 5
#define TPB 256
#define XTLD 136        // bf16 ld for xT tiles [d][row] (mult of 8)
#define ELD2 72         // bf16 ld for e tiles [code][d] (mult of 8)
#define SLD 164         // f32 ld for scoresT [code][row] (mult of 4)

// smem byte offsets
#define OFF_XTH 0                   // bf16[64][136] x3 (xT splits, persist)
#define OFF_XTM 17408
#define OFF_XTL 34816
#define OFF_UN  52224               // union: e tiles (3x11520) | scoresT f32[80][164]
#define OFF_EH  OFF_UN
#define OFF_EM  (OFF_UN + 11520)
#define OFF_EL  (OFF_UN + 23040)
#define OFF_SC  OFF_UN
#define OFF_N2A 104704              // f32[400]
#define OFF_RW  106304              // int[128]
#define OFF_MV  106816              // f32[128] merge values
#define OFF_MI  107328              // int[128] merge indices
#define SMEM_BYTES 107840

// precomputed e splits (h,m,l) and norms — __device__ scratch (allowed)
__device__ __nv_bfloat16 g_esp[3][KC * D];
__device__ float g_n2[KC];

// 3-way bf16 split: a ~= h + m + l (each captures ~8 mantissa bits)
static __device__ __forceinline__ void split3(float a, __nv_bfloat16 &h,
                                              __nv_bfloat16 &m, __nv_bfloat16 &l) {
    h = __float2bfloat16(a);
    float r = a - __bfloat162float(h);
    m = __float2bfloat16(r);
    float r2 = r - __bfloat162float(m);
    l = __float2bfloat16(r2);
}

__global__ void vq_prep_kernel(const float* __restrict__ emb) {
    int i = blockIdx.x * blockDim.x + threadIdx.x;   // 0..25599
    if (i < KC * D) {
        __nv_bfloat16 h, m, l;
        split3(emb[i], h, m, l);
        g_esp[0][i] = h;
        g_esp[1][i] = m;
        g_esp[2][i] = l;
    }
    if (i < KC) {
        const float* e = emb + (size_t)i * D;
        float s = 0.f;
        #pragma unroll 16
        for (int d = 0; d < D; d++) s = fmaf(e[d], e[d], s);
        g_n2[i] = -0.5f * s;
    }
}

__global__ void __launch_bounds__(TPB, 2)
vq_wmma_kernel(const float* __restrict__ x, const float* __restrict__ emb,
               float* __restrict__ out, int nrows) {
    extern __shared__ char sm[];
    float* n2a = (float*)(sm + OFF_N2A);
    int*   rw  = (int*)(sm + OFF_RW);
    float* mv  = (float*)(sm + OFF_MV);
    int*   mi  = (int*)(sm + OFF_MI);
    float* sc  = (float*)(sm + OFF_SC);

    const int tid = threadIdx.x;
    const int wid = tid >> 5;
    const int row0 = blockIdx.x * MTILE;

    // ---- norms to smem (precomputed) ----
    for (int i = tid; i < KC; i += TPB) n2a[i] = g_n2[i];

    // ---- stage xT once: [d][row] x3 splits; row-inner -> coalesced STS ----
    {
        const float4* xg = (const float4*)(x + (size_t)row0 * D);
        __nv_bfloat16* xth = (__nv_bfloat16*)(sm + OFF_XTH);
        __nv_bfloat16* xtm = (__nv_bfloat16*)(sm + OFF_XTM);
        __nv_bfloat16* xtl = (__nv_bfloat16*)(sm + OFF_XTL);
        for (int i = tid; i < MTILE * 16; i += TPB) {
            int row = i & 127, db = i >> 7;
            float4 v = xg[row * 16 + db];
            float vv[4] = {v.x, v.y, v.z, v.w};
            #pragma unroll
            for (int cc = 0; cc < 4; cc++) {
                __nv_bfloat16 h, m, l;
                split3(vv[cc], h, m, l);
                int o = (4 * db + cc) * XTLD + row;
                xth[o] = h; xtm[o] = m; xtl[o] = l;
            }
        }
    }

    // scan ownership: row = tid&127, half = tid>>7 (codes half*40..half*40+39)
    const int rowt = tid & 127;
    const int half = tid >> 7;
    float best = -3.4e38f;
    int bidx = 0;

    for (int c = 0; c < NCHUNKS; c++) {
        const int g0 = c * NCH;
        __syncthreads();   // prior scan / init done before union overwrite

        // ---- stage e chunk: pure uint4 copies of precomputed splits ----
        // 3 splits x 80 codes x 8 uint4 (64 bf16 = 128B) -> stride-ELD2 rows
        for (int i = tid; i < 3 * NCH * 8; i += TPB) {
            int split = i / (NCH * 8);
            int idx = i - split * (NCH * 8);
            int code = idx >> 3, c8 = idx & 7;
            uint4 v = *(const uint4*)(&g_esp[split][(size_t)(g0 + code) * D + c8 * 8]);
            *(uint4*)(sm + OFF_EH + split * 11520 + (code * ELD2 + c8 * 8) * 2) = v;
        }
        __syncthreads();

        // ---- MMAs: scoresT = E * X^T.  A = e [code][d] rm, B = xT [d][row] rm ----
        wmma::fragment<wmma::accumulator, 16, 16, 16, float> acc[5];
        #pragma unroll
        for (int nf = 0; nf < 5; nf++) wmma::fill_fragment(acc[nf], 0.0f);

        const __nv_bfloat16* eh  = (const __nv_bfloat16*)(sm + OFF_EH);
        const __nv_bfloat16* em  = (const __nv_bfloat16*)(sm + OFF_EM);
        const __nv_bfloat16* el  = (const __nv_bfloat16*)(sm + OFF_EL);
        const __nv_bfloat16* xth = (const __nv_bfloat16*)(sm + OFF_XTH) + wid * 16;
        const __nv_bfloat16* xtm = (const __nv_bfloat16*)(sm + OFF_XTM) + wid * 16;
        const __nv_bfloat16* xtl = (const __nv_bfloat16*)(sm + OFF_XTL) + wid * 16;

        #pragma unroll
        for (int k = 0; k < 4; k++) {
            wmma::fragment<wmma::matrix_b, 16, 16, 16, __nv_bfloat16, wmma::row_major> bh, bm, bl;
            wmma::load_matrix_sync(bh, xth + k * 16 * XTLD, XTLD);
            wmma::load_matrix_sync(bm, xtm + k * 16 * XTLD, XTLD);
            wmma::load_matrix_sync(bl, xtl + k * 16 * XTLD, XTLD);
            #pragma unroll
            for (int nf = 0; nf < 5; nf++) {
                wmma::fragment<wmma::matrix_a, 16, 16, 16, __nv_bfloat16, wmma::row_major> ah, am, al;
                wmma::load_matrix_sync(ah, eh + nf * 16 * ELD2 + k * 16, ELD2);
                wmma::load_matrix_sync(am, em + nf * 16 * ELD2 + k * 16, ELD2);
                wmma::load_matrix_sync(al, el + nf * 16 * ELD2 + k * 16, ELD2);
                wmma::mma_sync(acc[nf], ah, bh, acc[nf]);   // hh
                wmma::mma_sync(acc[nf], ah, bm, acc[nf]);   // hm
                wmma::mma_sync(acc[nf], am, bh, acc[nf]);   // mh
                wmma::mma_sync(acc[nf], am, bm, acc[nf]);   // mm
                wmma::mma_sync(acc[nf], ah, bl, acc[nf]);   // hl
                wmma::mma_sync(acc[nf], al, bh, acc[nf]);   // lh
            }
        }

        __syncthreads();   // e readers done before scoresT overwrite union
        #pragma unroll
        for (int nf = 0; nf < 5; nf++)
            wmma::store_matrix_sync(sc + nf * 16 * SLD + wid * 16, acc[nf], SLD,
                                    wmma::mem_row_major);
        __syncthreads();

        // ---- split scan: all 256 threads, 40 codes each; conflict-free LDS ----
        {
            const int jb = half * 40;
            #pragma unroll 8
            for (int j = 0; j < 40; j++) {
                int jj = jb + j;
                float s = sc[jj * SLD + rowt] + n2a[g0 + jj];
                // strict >, ascending jj within subsequence
                if (s > best) { best = s; bidx = g0 + jj; }
            }
        }
    }

    // ---- merge halves: (score, lower index) rule == global first-max ----
    __syncthreads();
    if (half == 1) { mv[rowt] = best; mi[rowt] = bidx; }
    __syncthreads();
    if (tid < MTILE) {
        float s2 = mv[tid];
        int i2 = mi[tid];
        if (s2 > best || (s2 == best && i2 < bidx)) { best = s2; bidx = i2; }
        rw[tid] = bidx;
    }
    __syncthreads();

    // ---- winners: cooperative coalesced gather ----
    const float4* eg = (const float4*)emb;
    float4* og = (float4*)(out + (size_t)row0 * D);
    for (int i = tid; i < MTILE * 16; i += TPB) {
        int r = i >> 4, q = i & 15;
        og[r * 16 + q] = eg[(size_t)rw[r] * 16 + q];
    }
}

extern "C" void kernel_launch(void* const* d_in, const int* in_sizes, int n_in,
                              void* d_out, int out_size) {
    const float* x   = (const float*)d_in[0];
    const float* emb = (const float*)d_in[1];
    float* out = (float*)d_out;

    int nrows = in_sizes[0] / D;   // 262144, divisible by MTILE

    cudaFuncSetAttribute(vq_wmma_kernel,
                         cudaFuncAttributeMaxDynamicSharedMemorySize, SMEM_BYTES);

    vq_prep_kernel<<<(KC * D + TPB - 1) / TPB, TPB>>>(emb);   // 100 blocks

    int blocks = nrows / MTILE;    // 2048
    vq_wmma_kernel<<<blocks, TPB, SMEM_BYTES>>>(x, emb, out, nrows);
}